// round 10
// baseline (speedup 1.0000x reference)
#include <cuda_runtime.h>
#include <cuda_fp16.h>
#include <math.h>
#include <stdint.h>

#define N_NODES 59392
#define HID     256
#define DOUT    232
#define DH      116
#define NPG     116
#define NGRAPH  512
#define QS      928           // qkvs row stride (floats)
#define NPAD    1024          // padded GEMM N

// GEMM tiling
#define TM 128
#define TN 128
#define KC 32
#define NCH (HID / KC)        // 8
#define NSTG 4
// smem strides in halves (conflict-free ldmatrix)
#define ASTR 40               // 32 + 8
#define BSTR 136              // 128 + 8
#define A_T (TM * ASTR)       // 5120 halves
#define B_T (KC * BSTR)       // 4352 halves
#define STG_H (A_T + B_T)     // 9472 halves per stage
#define SM_BYTES (NSTG * STG_H * 2)   // 75776 B

// ---------------- device scratch (no allocations allowed) ----------------
__device__ __align__(16) __half g_hf16[(size_t)N_NODES * HID];   // h in fp16
__device__ __align__(16) __half g_Wh[HID * NPAD];                // [256,1024] q|k|v|s fp16, zero pad
__device__ __align__(16) float  g_qkvs[(size_t)N_NODES * QS];    // [N,928] q|k|v|s fp32
__device__ __align__(16) float  g_hproj[(size_t)N_NODES * DOUT]; // [N,232]
__device__ float g_e[N_NODES];                                   // per-node mean
__device__ int   g_is64;                                         // edge_index dtype flag

// ---------------- helpers ----------------
__device__ __forceinline__ uint32_t s2u(const void* p) {
    uint32_t a;
    asm("{ .reg .u64 t; cvta.to.shared.u64 t, %1; cvt.u32.u64 %0, t; }"
        : "=r"(a) : "l"(p));
    return a;
}
__device__ __forceinline__ void cp16(uint32_t saddr, const void* gaddr) {
    asm volatile("cp.async.cg.shared.global [%0], [%1], 16;"
                 :: "r"(saddr), "l"(gaddr));
}
__device__ __forceinline__ void ldm4(uint32_t& r0, uint32_t& r1, uint32_t& r2,
                                     uint32_t& r3, uint32_t a) {
    asm volatile("ldmatrix.sync.aligned.m8n8.x4.shared.b16 {%0,%1,%2,%3}, [%4];"
                 : "=r"(r0), "=r"(r1), "=r"(r2), "=r"(r3) : "r"(a));
}
__device__ __forceinline__ void ldm4t(uint32_t& r0, uint32_t& r1, uint32_t& r2,
                                      uint32_t& r3, uint32_t a) {
    asm volatile("ldmatrix.sync.aligned.m8n8.x4.trans.shared.b16 {%0,%1,%2,%3}, [%4];"
                 : "=r"(r0), "=r"(r1), "=r"(r2), "=r"(r3) : "r"(a));
}
__device__ __forceinline__ void mma_f16(float& d0, float& d1, float& d2, float& d3,
                                        uint32_t a0, uint32_t a1, uint32_t a2, uint32_t a3,
                                        uint32_t b0, uint32_t b1) {
    asm volatile("mma.sync.aligned.m16n8k16.row.col.f32.f16.f16.f32 "
                 "{%0,%1,%2,%3}, {%4,%5,%6,%7}, {%8,%9}, {%0,%1,%2,%3};"
                 : "+f"(d0), "+f"(d1), "+f"(d2), "+f"(d3)
                 : "r"(a0), "r"(a1), "r"(a2), "r"(a3), "r"(b0), "r"(b1));
}
__device__ __forceinline__ float dot4(float4 a, float4 b) {
    return a.x * b.x + a.y * b.y + a.z * b.z + a.w * b.w;
}

// ---------------- edge_index dtype probe ----------------
__global__ void detect_dtype(const int* __restrict__ e32) {
    if (threadIdx.x == 0 && blockIdx.x == 0) {
        int z = (e32[1] == 0) & (e32[3] == 0) & (e32[5] == 0) &
                (e32[7] == 0) & (e32[9] == 0);
        g_is64 = z;
    }
}

// ---------------- convert h -> fp16 ----------------
__global__ __launch_bounds__(256) void conv_h(const float* __restrict__ h) {
    size_t i = ((size_t)blockIdx.x * blockDim.x + threadIdx.x) * 4;
    if (i < (size_t)N_NODES * HID) {
        float4 v = *(const float4*)(h + i);
        __half2* dst = (__half2*)(g_hf16 + i);
        dst[0] = __floats2half2_rn(v.x, v.y);
        dst[1] = __floats2half2_rn(v.z, v.w);
    }
}

// ---------------- pack Wq|Wk|Wv|Ws into g_Wh[256,1024] fp16 ----------------
__global__ void pack_w(const float* __restrict__ Wq, const float* __restrict__ Wk,
                       const float* __restrict__ Wv, const float* __restrict__ Ws) {
    int idx = blockIdx.x * blockDim.x + threadIdx.x;
    if (idx >= HID * DOUT) return;
    int k = idx / DOUT, n = idx % DOUT;
    __half* row = g_Wh + (size_t)k * NPAD;
    row[n]       = __float2half_rn(Wq[idx]);
    row[232 + n] = __float2half_rn(Wk[idx]);
    row[464 + n] = __float2half_rn(Wv[idx]);
    row[696 + n] = __float2half_rn(Ws[idx]);
}

// ---------------- fp16 HGEMM: 4-stage cp.async pipeline ----------------
__device__ __forceinline__ void load_chunk(uint32_t stg, int row0, int col0,
                                           int k0, int tid) {
    uint32_t as = stg, bs = stg + A_T * 2;
#pragma unroll
    for (int j = 0; j < 2; j++) {                 // A: 512 cp16
        int idx = tid + 256 * j;
        int m  = idx >> 2;
        int kq = (idx & 3) * 8;
        cp16(as + (m * ASTR + kq) * 2,
             g_hf16 + (size_t)(row0 + m) * HID + k0 + kq);
    }
#pragma unroll
    for (int j = 0; j < 2; j++) {                 // B: 512 cp16
        int idx = tid + 256 * j;
        int kr = idx >> 4;
        int n  = (idx & 15) * 8;
        cp16(bs + (kr * BSTR + n) * 2,
             g_Wh + (size_t)(k0 + kr) * NPAD + col0 + n);
    }
    asm volatile("cp.async.commit_group;" ::: "memory");
}

__device__ __forceinline__ void compute_chunk(uint32_t stg, int wm, int wn,
                                              int lane, float d[4][4][4]) {
    uint32_t as = stg, bs = stg + A_T * 2;
    const int lrow = lane & 15;
    const int lsel = (lane >> 4) << 3;
#pragma unroll
    for (int kk = 0; kk < KC; kk += 16) {
        uint32_t af[4][4], bf[4][2];
#pragma unroll
        for (int mi = 0; mi < 4; mi++) {
            uint32_t a = as + ((wm + mi * 16 + lrow) * ASTR + kk + lsel) * 2;
            ldm4(af[mi][0], af[mi][1], af[mi][2], af[mi][3], a);
        }
#pragma unroll
        for (int nj = 0; nj < 2; nj++) {
            uint32_t a = bs + ((kk + lrow) * BSTR + wn + nj * 16 + lsel) * 2;
            uint32_t r0, r1, r2, r3;
            ldm4t(r0, r1, r2, r3, a);
            bf[nj * 2][0] = r0;     bf[nj * 2][1] = r1;
            bf[nj * 2 + 1][0] = r2; bf[nj * 2 + 1][1] = r3;
        }
#pragma unroll
        for (int mi = 0; mi < 4; mi++)
#pragma unroll
            for (int ni = 0; ni < 4; ni++)
                mma_f16(d[mi][ni][0], d[mi][ni][1], d[mi][ni][2], d[mi][ni][3],
                        af[mi][0], af[mi][1], af[mi][2], af[mi][3],
                        bf[ni][0], bf[ni][1]);
    }
}

__global__ __launch_bounds__(256) void gemm_hmma() {
    extern __shared__ __half smem[];
    const uint32_t sbase = s2u(smem);

    const int tid  = threadIdx.x;
    const int wid  = tid >> 5;
    const int lane = tid & 31;
    const int wm = (wid & 1) * 64;
    const int wn = (wid >> 1) * 32;
    const int r  = lane >> 2;
    const int c  = lane & 3;
    const int row0 = blockIdx.y * TM;
    const int col0 = blockIdx.x * TN;

    float d[4][4][4];
#pragma unroll
    for (int mi = 0; mi < 4; mi++)
#pragma unroll
        for (int ni = 0; ni < 4; ni++)
#pragma unroll
            for (int t = 0; t < 4; t++) d[mi][ni][t] = 0.f;

    // prime 3 stages
    load_chunk(sbase + 0 * STG_H * 2, row0, col0, 0 * KC, tid);
    load_chunk(sbase + 1 * STG_H * 2, row0, col0, 1 * KC, tid);
    load_chunk(sbase + 2 * STG_H * 2, row0, col0, 2 * KC, tid);

#pragma unroll
    for (int ch = 0; ch < NCH; ch++) {
        if (ch <= NCH - 3)
            asm volatile("cp.async.wait_group 2;" ::: "memory");
        else if (ch == NCH - 2)
            asm volatile("cp.async.wait_group 1;" ::: "memory");
        else
            asm volatile("cp.async.wait_group 0;" ::: "memory");
        __syncthreads();
        if (ch + 3 < NCH)
            load_chunk(sbase + ((ch + 3) & 3) * STG_H * 2, row0, col0,
                       (ch + 3) * KC, tid);
        compute_chunk(sbase + (ch & 3) * STG_H * 2, wm, wn, lane, d);
    }

    // epilogue: predicated stores into stride-928 qkvs
    const int c2 = c * 2;
#pragma unroll
    for (int mi = 0; mi < 4; mi++) {
#pragma unroll
        for (int ni = 0; ni < 4; ni++) {
            int row = row0 + wm + mi * 16 + r;
            int col = col0 + wn + ni * 8 + c2;
            if (col < QS) {
                *(float2*)&g_qkvs[(size_t)row * QS + col] =
                    make_float2(d[mi][ni][0], d[mi][ni][1]);
                *(float2*)&g_qkvs[(size_t)(row + 8) * QS + col] =
                    make_float2(d[mi][ni][2], d[mi][ni][3]);
            }
        }
    }
}

// ---------------- per-node edge attention (one warp per node, float4, batched) ----------------
__global__ __launch_bounds__(256) void attn_kernel(const int* __restrict__ e32) {
    const int warp = threadIdx.x >> 5;
    const int lane = threadIdx.x & 31;
    const int node = blockIdx.x * 8 + warp;
    if (node >= N_NODES) return;
    const int is64 = g_is64;
    const bool v2 = lane < 26;          // second f4 valid
    const bool h0 = lane < 29;          // first f4 belongs to head 0
    const float4 z4 = make_float4(0.f, 0.f, 0.f, 0.f);

    const float4* row4 = (const float4*)(g_qkvs + (size_t)node * QS);
    float4 q0 = row4[lane];
    float4 q1 = v2 ? row4[lane + 32] : z4;

    int src[8];
#pragma unroll
    for (int e = 0; e < 8; e++) {
        int ei = node * 8 + e;
        src[e] = is64 ? e32[2 * ei] : e32[ei];
    }

    float s0[8], s1[8];
#pragma unroll
    for (int g = 0; g < 2; g++) {
        float4 k0[4], k1[4];
#pragma unroll
        for (int e = 0; e < 4; e++) {
            const float4* kp = (const float4*)(g_qkvs + (size_t)src[g * 4 + e] * QS + 232);
            k0[e] = kp[lane];
            k1[e] = v2 ? kp[lane + 32] : z4;
        }
#pragma unroll
        for (int e = 0; e < 4; e++) {
            float p0 = dot4(q0, k0[e]);
            float p1 = dot4(q1, k1[e]);
            float a0 = h0 ? p0 : 0.f;
            float a1 = h0 ? p1 : p0 + p1;
#pragma unroll
            for (int o = 16; o > 0; o >>= 1) {
                a0 += __shfl_xor_sync(0xFFFFFFFFu, a0, o);
                a1 += __shfl_xor_sync(0xFFFFFFFFu, a1, o);
            }
            s0[g * 4 + e] = a0; s1[g * 4 + e] = a1;
        }
    }

    const float scale = rsqrtf((float)DH);
    float m0 = -1e30f, m1 = -1e30f;
#pragma unroll
    for (int e = 0; e < 8; e++) {
        s0[e] *= scale; s1[e] *= scale;
        m0 = fmaxf(m0, s0[e]); m1 = fmaxf(m1, s1[e]);
    }
    float sum0 = 0.f, sum1 = 0.f;
    float w0[8], w1[8];
#pragma unroll
    for (int e = 0; e < 8; e++) {
        w0[e] = expf(s0[e] - m0); sum0 += w0[e];
        w1[e] = expf(s1[e] - m1); sum1 += w1[e];
    }
    float inv0 = 1.f / (sum0 + 1e-16f);
    float inv1 = 1.f / (sum1 + 1e-16f);
#pragma unroll
    for (int e = 0; e < 8; e++) { w0[e] *= inv0; w1[e] *= inv1; }

    // skip init (Ws proj at f4 offset 174), then accumulate alpha*v (batched)
    float4 acc0 = row4[174 + lane];
    float4 acc1 = v2 ? row4[174 + 32 + lane] : z4;
#pragma unroll
    for (int g = 0; g < 2; g++) {
        float4 vv0[4], vv1[4];
#pragma unroll
        for (int e = 0; e < 4; e++) {
            const float4* vp = (const float4*)(g_qkvs + (size_t)src[g * 4 + e] * QS + 464);
            vv0[e] = vp[lane];
            vv1[e] = v2 ? vp[lane + 32] : z4;
        }
#pragma unroll
        for (int e = 0; e < 4; e++) {
            float wf = h0 ? w0[g * 4 + e] : w1[g * 4 + e];
            float ws = w1[g * 4 + e];
            acc0.x += wf * vv0[e].x; acc0.y += wf * vv0[e].y;
            acc0.z += wf * vv0[e].z; acc0.w += wf * vv0[e].w;
            acc1.x += ws * vv1[e].x; acc1.y += ws * vv1[e].y;
            acc1.z += ws * vv1[e].z; acc1.w += ws * vv1[e].w;
        }
    }

    float part = acc0.x + acc0.y + acc0.z + acc0.w
               + acc1.x + acc1.y + acc1.z + acc1.w;
#pragma unroll
    for (int o = 16; o > 0; o >>= 1) part += __shfl_xor_sync(0xFFFFFFFFu, part, o);

    float4* hp4 = (float4*)(g_hproj + (size_t)node * DOUT);
    hp4[lane] = acc0;
    if (v2) hp4[lane + 32] = acc1;
    if (lane == 0) g_e[node] = part * (1.f / 232.f);
}

// ---------------- per-graph softmax + weighting (warp-per-row, float4) ----------------
__global__ __launch_bounds__(128) void graph_softmax(float* __restrict__ out_alpha,
                                                     float* __restrict__ out_hw) {
    const int g = blockIdx.x;
    const int tid = threadIdx.x;
    const int wid = tid >> 5;
    const int lane = tid & 31;
    __shared__ float sh[128];
    __shared__ float salpha[NPG];
    const int base = g * NPG;

    float v = (tid < NPG) ? g_e[base + tid] : -1e30f;
    sh[tid] = v; __syncthreads();
    for (int o = 64; o > 0; o >>= 1) {
        if (tid < o) sh[tid] = fmaxf(sh[tid], sh[tid + o]);
        __syncthreads();
    }
    float m = sh[0]; __syncthreads();
    float ex = (tid < NPG) ? expf(v - m) : 0.f;
    sh[tid] = ex; __syncthreads();
    for (int o = 64; o > 0; o >>= 1) {
        if (tid < o) sh[tid] += sh[tid + o];
        __syncthreads();
    }
    float s = sh[0];
    float alpha = ex / s;
    if (tid < NPG) {
        salpha[tid] = alpha;
        out_alpha[base + tid] = alpha;
    }
    __syncthreads();

    for (int r = wid; r < NPG; r += 4) {
        float a = salpha[r];
        const float4* s4 = (const float4*)(g_hproj + (size_t)(base + r) * DOUT);
        float4* d4 = (float4*)(out_hw + (size_t)(base + r) * DOUT);
        float4 x = s4[lane];
        d4[lane] = make_float4(a * x.x, a * x.y, a * x.z, a * x.w);
        if (lane < 26) {
            float4 y = s4[lane + 32];
            d4[lane + 32] = make_float4(a * y.x, a * y.y, a * y.z, a * y.w);
        }
    }
}

// ---------------- launch ----------------
extern "C" void kernel_launch(void* const* d_in, const int* in_sizes, int n_in,
                              void* d_out, int out_size) {
    const float* h    = (const float*)d_in[0];
    const int*   edge = (const int*)  d_in[1];   // row 0 = src
    const float* Wq = (const float*)d_in[3];
    const float* Wk = (const float*)d_in[4];
    const float* Wv = (const float*)d_in[5];
    const float* Ws = (const float*)d_in[6];
    float* out = (float*)d_out;   // [0:59392) alpha_map, then h_weighted [N,232]

    cudaFuncSetAttribute(gemm_hmma, cudaFuncAttributeMaxDynamicSharedMemorySize,
                         SM_BYTES);

    detect_dtype<<<1, 32>>>(edge);
    conv_h<<<(N_NODES * HID / 4 + 255) / 256, 256>>>(h);
    pack_w<<<(HID * DOUT + 255) / 256, 256>>>(Wq, Wk, Wv, Ws);
    dim3 ggrid(NPAD / TN, N_NODES / TM);   // (8, 464)
    gemm_hmma<<<ggrid, 256, SM_BYTES>>>();
    attn_kernel<<<N_NODES / 8, 256>>>(edge);
    graph_softmax<<<NGRAPH, 128>>>(out, out + N_NODES);
}

// round 13
// speedup vs baseline: 1.0579x; 1.0579x over previous
#include <cuda_runtime.h>
#include <cuda_fp16.h>
#include <math.h>
#include <stdint.h>

#define N_NODES 59392
#define HID     256
#define DOUT    232
#define DH      116
#define NPG     116
#define NGRAPH  512
#define QS      928           // qkvs row stride (floats)
#define NPAD    1024          // padded GEMM N
#define KVS     464           // kv16 row stride (halves): k[232] | v[232]

// GEMM tiling
#define TM 128
#define TN 128
#define KC 32
#define NCH (HID / KC)        // 8
#define NSTG 4
#define ASTR 40               // 32 + 8 halves
#define BSTR 136              // 128 + 8 halves
#define A_T (TM * ASTR)
#define B_T (KC * BSTR)
#define STG_H (A_T + B_T)
#define SM_BYTES (NSTG * STG_H * 2)   // 75776 B

// ---------------- device scratch (no allocations allowed) ----------------
__device__ __align__(16) __half g_hf16[(size_t)N_NODES * HID];   // h in fp16
__device__ __align__(16) __half g_Wh[HID * NPAD];                // packed weights fp16
__device__ __align__(16) float  g_qkvs[(size_t)N_NODES * QS];    // [N,928] fp32
__device__ __align__(16) __half g_kv16[(size_t)N_NODES * KVS];   // [N,464] fp16 k|v
__device__ __align__(16) float  g_hproj[(size_t)N_NODES * DOUT]; // [N,232]
__device__ float g_e[N_NODES];
__device__ int   g_is64;

// ---------------- helpers ----------------
__device__ __forceinline__ uint32_t s2u(const void* p) {
    uint32_t a;
    asm("{ .reg .u64 t; cvta.to.shared.u64 t, %1; cvt.u32.u64 %0, t; }"
        : "=r"(a) : "l"(p));
    return a;
}
__device__ __forceinline__ void cp16(uint32_t saddr, const void* gaddr) {
    asm volatile("cp.async.cg.shared.global [%0], [%1], 16;"
                 :: "r"(saddr), "l"(gaddr));
}
__device__ __forceinline__ void ldm4(uint32_t& r0, uint32_t& r1, uint32_t& r2,
                                     uint32_t& r3, uint32_t a) {
    asm volatile("ldmatrix.sync.aligned.m8n8.x4.shared.b16 {%0,%1,%2,%3}, [%4];"
                 : "=r"(r0), "=r"(r1), "=r"(r2), "=r"(r3) : "r"(a));
}
__device__ __forceinline__ void ldm4t(uint32_t& r0, uint32_t& r1, uint32_t& r2,
                                      uint32_t& r3, uint32_t a) {
    asm volatile("ldmatrix.sync.aligned.m8n8.x4.trans.shared.b16 {%0,%1,%2,%3}, [%4];"
                 : "=r"(r0), "=r"(r1), "=r"(r2), "=r"(r3) : "r"(a));
}
__device__ __forceinline__ void mma_f16(float& d0, float& d1, float& d2, float& d3,
                                        uint32_t a0, uint32_t a1, uint32_t a2, uint32_t a3,
                                        uint32_t b0, uint32_t b1) {
    asm volatile("mma.sync.aligned.m16n8k16.row.col.f32.f16.f16.f32 "
                 "{%0,%1,%2,%3}, {%4,%5,%6,%7}, {%8,%9}, {%0,%1,%2,%3};"
                 : "+f"(d0), "+f"(d1), "+f"(d2), "+f"(d3)
                 : "r"(a0), "r"(a1), "r"(a2), "r"(a3), "r"(b0), "r"(b1));
}
// dot of fp32 q-float4 against 4 halves packed in uint2
__device__ __forceinline__ float dot4h(float4 q, uint2 kv) {
    float2 f01 = __half22float2(*(const __half2*)&kv.x);
    float2 f23 = __half22float2(*(const __half2*)&kv.y);
    return q.x * f01.x + q.y * f01.y + q.z * f23.x + q.w * f23.y;
}

// ---------------- edge_index dtype probe ----------------
__global__ void detect_dtype(const int* __restrict__ e32) {
    if (threadIdx.x == 0 && blockIdx.x == 0) {
        int z = (e32[1] == 0) & (e32[3] == 0) & (e32[5] == 0) &
                (e32[7] == 0) & (e32[9] == 0);
        g_is64 = z;
    }
}

// ---------------- convert h -> fp16 ----------------
__global__ __launch_bounds__(256) void conv_h(const float* __restrict__ h) {
    size_t i = ((size_t)blockIdx.x * blockDim.x + threadIdx.x) * 4;
    if (i < (size_t)N_NODES * HID) {
        float4 v = *(const float4*)(h + i);
        __half2* dst = (__half2*)(g_hf16 + i);
        dst[0] = __floats2half2_rn(v.x, v.y);
        dst[1] = __floats2half2_rn(v.z, v.w);
    }
}

// ---------------- pack Wq|Wk|Wv|Ws into g_Wh[256,1024] fp16 ----------------
__global__ void pack_w(const float* __restrict__ Wq, const float* __restrict__ Wk,
                       const float* __restrict__ Wv, const float* __restrict__ Ws) {
    int idx = blockIdx.x * blockDim.x + threadIdx.x;
    if (idx >= HID * DOUT) return;
    int k = idx / DOUT, n = idx % DOUT;
    __half* row = g_Wh + (size_t)k * NPAD;
    row[n]       = __float2half_rn(Wq[idx]);
    row[232 + n] = __float2half_rn(Wk[idx]);
    row[464 + n] = __float2half_rn(Wv[idx]);
    row[696 + n] = __float2half_rn(Ws[idx]);
}

// ---------------- fp16 HGEMM: 4-stage cp.async pipeline ----------------
__device__ __forceinline__ void load_chunk(uint32_t stg, int row0, int col0,
                                           int k0, int tid) {
    uint32_t as = stg, bs = stg + A_T * 2;
#pragma unroll
    for (int j = 0; j < 2; j++) {
        int idx = tid + 256 * j;
        int m  = idx >> 2;
        int kq = (idx & 3) * 8;
        cp16(as + (m * ASTR + kq) * 2,
             g_hf16 + (size_t)(row0 + m) * HID + k0 + kq);
    }
#pragma unroll
    for (int j = 0; j < 2; j++) {
        int idx = tid + 256 * j;
        int kr = idx >> 4;
        int n  = (idx & 15) * 8;
        cp16(bs + (kr * BSTR + n) * 2,
             g_Wh + (size_t)(k0 + kr) * NPAD + col0 + n);
    }
    asm volatile("cp.async.commit_group;" ::: "memory");
}

__device__ __forceinline__ void compute_chunk(uint32_t stg, int wm, int wn,
                                              int lane, float d[4][4][4]) {
    uint32_t as = stg, bs = stg + A_T * 2;
    const int lrow = lane & 15;
    const int lsel = (lane >> 4) << 3;
#pragma unroll
    for (int kk = 0; kk < KC; kk += 16) {
        uint32_t af[4][4], bf[4][2];
#pragma unroll
        for (int mi = 0; mi < 4; mi++) {
            uint32_t a = as + ((wm + mi * 16 + lrow) * ASTR + kk + lsel) * 2;
            ldm4(af[mi][0], af[mi][1], af[mi][2], af[mi][3], a);
        }
#pragma unroll
        for (int nj = 0; nj < 2; nj++) {
            uint32_t a = bs + ((kk + lrow) * BSTR + wn + nj * 16 + lsel) * 2;
            uint32_t r0, r1, r2, r3;
            ldm4t(r0, r1, r2, r3, a);
            bf[nj * 2][0] = r0;     bf[nj * 2][1] = r1;
            bf[nj * 2 + 1][0] = r2; bf[nj * 2 + 1][1] = r3;
        }
#pragma unroll
        for (int mi = 0; mi < 4; mi++)
#pragma unroll
            for (int ni = 0; ni < 4; ni++)
                mma_f16(d[mi][ni][0], d[mi][ni][1], d[mi][ni][2], d[mi][ni][3],
                        af[mi][0], af[mi][1], af[mi][2], af[mi][3],
                        bf[ni][0], bf[ni][1]);
    }
}

__global__ __launch_bounds__(256) void gemm_hmma() {
    extern __shared__ __half smem[];
    const uint32_t sbase = s2u(smem);

    const int tid  = threadIdx.x;
    const int wid  = tid >> 5;
    const int lane = tid & 31;
    const int wm = (wid & 1) * 64;
    const int wn = (wid >> 1) * 32;
    const int r  = lane >> 2;
    const int c  = lane & 3;
    const int row0 = blockIdx.y * TM;
    const int col0 = blockIdx.x * TN;

    float d[4][4][4];
#pragma unroll
    for (int mi = 0; mi < 4; mi++)
#pragma unroll
        for (int ni = 0; ni < 4; ni++)
#pragma unroll
            for (int t = 0; t < 4; t++) d[mi][ni][t] = 0.f;

    load_chunk(sbase + 0 * STG_H * 2, row0, col0, 0 * KC, tid);
    load_chunk(sbase + 1 * STG_H * 2, row0, col0, 1 * KC, tid);
    load_chunk(sbase + 2 * STG_H * 2, row0, col0, 2 * KC, tid);

#pragma unroll
    for (int ch = 0; ch < NCH; ch++) {
        if (ch <= NCH - 3)
            asm volatile("cp.async.wait_group 2;" ::: "memory");
        else if (ch == NCH - 2)
            asm volatile("cp.async.wait_group 1;" ::: "memory");
        else
            asm volatile("cp.async.wait_group 0;" ::: "memory");
        __syncthreads();
        if (ch + 3 < NCH)
            load_chunk(sbase + ((ch + 3) & 3) * STG_H * 2, row0, col0,
                       (ch + 3) * KC, tid);
        compute_chunk(sbase + (ch & 3) * STG_H * 2, wm, wn, lane, d);
    }

    // epilogue: fp32 qkvs + fp16 k|v side-buffer
    const int c2 = c * 2;
#pragma unroll
    for (int mi = 0; mi < 4; mi++) {
#pragma unroll
        for (int ni = 0; ni < 4; ni++) {
            int row = row0 + wm + mi * 16 + r;
            int col = col0 + wn + ni * 8 + c2;
            if (col < QS) {
                *(float2*)&g_qkvs[(size_t)row * QS + col] =
                    make_float2(d[mi][ni][0], d[mi][ni][1]);
                *(float2*)&g_qkvs[(size_t)(row + 8) * QS + col] =
                    make_float2(d[mi][ni][2], d[mi][ni][3]);
                if (col >= 232 && col < 696) {
                    *(__half2*)&g_kv16[(size_t)row * KVS + (col - 232)] =
                        __floats2half2_rn(d[mi][ni][0], d[mi][ni][1]);
                    *(__half2*)&g_kv16[(size_t)(row + 8) * KVS + (col - 232)] =
                        __floats2half2_rn(d[mi][ni][2], d[mi][ni][3]);
                }
            }
        }
    }
}

// ---------------- per-node edge attention (fp16 k/v gathers) ----------------
__global__ __launch_bounds__(256) void attn_kernel(const int* __restrict__ e32) {
    const int warp = threadIdx.x >> 5;
    const int lane = threadIdx.x & 31;
    const int node = blockIdx.x * 8 + warp;
    if (node >= N_NODES) return;
    const int is64 = g_is64;
    const bool v2 = lane < 26;          // second 4-group valid (58 groups total)
    const bool h0 = lane < 29;          // first group belongs to head 0
    const float4 z4 = make_float4(0.f, 0.f, 0.f, 0.f);
    const uint2  z2 = make_uint2(0u, 0u);

    const float4* row4 = (const float4*)(g_qkvs + (size_t)node * QS);
    float4 q0 = row4[lane];
    float4 q1 = v2 ? row4[lane + 32] : z4;

    int src[8];
#pragma unroll
    for (int e = 0; e < 8; e++) {
        int ei = node * 8 + e;
        src[e] = is64 ? e32[2 * ei] : e32[ei];
    }

    float s0[8], s1[8];
#pragma unroll
    for (int g = 0; g < 2; g++) {
        uint2 k0[4], k1[4];
#pragma unroll
        for (int e = 0; e < 4; e++) {
            const uint2* kp = (const uint2*)(g_kv16 + (size_t)src[g * 4 + e] * KVS);
            k0[e] = kp[lane];
            k1[e] = v2 ? kp[lane + 32] : z2;
        }
#pragma unroll
        for (int e = 0; e < 4; e++) {
            float p0 = dot4h(q0, k0[e]);
            float p1 = dot4h(q1, k1[e]);
            float a0 = h0 ? p0 : 0.f;
            float a1 = h0 ? p1 : p0 + p1;
#pragma unroll
            for (int o = 16; o > 0; o >>= 1) {
                a0 += __shfl_xor_sync(0xFFFFFFFFu, a0, o);
                a1 += __shfl_xor_sync(0xFFFFFFFFu, a1, o);
            }
            s0[g * 4 + e] = a0; s1[g * 4 + e] = a1;
        }
    }

    const float scale = rsqrtf((float)DH);
    float m0 = -1e30f, m1 = -1e30f;
#pragma unroll
    for (int e = 0; e < 8; e++) {
        s0[e] *= scale; s1[e] *= scale;
        m0 = fmaxf(m0, s0[e]); m1 = fmaxf(m1, s1[e]);
    }
    float sum0 = 0.f, sum1 = 0.f;
    float w0[8], w1[8];
#pragma unroll
    for (int e = 0; e < 8; e++) {
        w0[e] = expf(s0[e] - m0); sum0 += w0[e];
        w1[e] = expf(s1[e] - m1); sum1 += w1[e];
    }
    float inv0 = 1.f / (sum0 + 1e-16f);
    float inv1 = 1.f / (sum1 + 1e-16f);
#pragma unroll
    for (int e = 0; e < 8; e++) { w0[e] *= inv0; w1[e] *= inv1; }

    // skip init (fp32), accumulate alpha*v with fp16 v gathers
    float4 acc0 = row4[174 + lane];
    float4 acc1 = v2 ? row4[174 + 32 + lane] : z4;
#pragma unroll
    for (int g = 0; g < 2; g++) {
        uint2 vv0[4], vv1[4];
#pragma unroll
        for (int e = 0; e < 4; e++) {
            const uint2* vp = (const uint2*)(g_kv16 + (size_t)src[g * 4 + e] * KVS + 232);
            vv0[e] = vp[lane];
            vv1[e] = v2 ? vp[lane + 32] : z2;
        }
#pragma unroll
        for (int e = 0; e < 4; e++) {
            float wf = h0 ? w0[g * 4 + e] : w1[g * 4 + e];
            float ws = w1[g * 4 + e];
            float2 a01 = __half22float2(*(const __half2*)&vv0[e].x);
            float2 a23 = __half22float2(*(const __half2*)&vv0[e].y);
            acc0.x += wf * a01.x; acc0.y += wf * a01.y;
            acc0.z += wf * a23.x; acc0.w += wf * a23.y;
            float2 b01 = __half22float2(*(const __half2*)&vv1[e].x);
            float2 b23 = __half22float2(*(const __half2*)&vv1[e].y);
            acc1.x += ws * b01.x; acc1.y += ws * b01.y;
            acc1.z += ws * b23.x; acc1.w += ws * b23.y;
        }
    }

    float part = acc0.x + acc0.y + acc0.z + acc0.w
               + acc1.x + acc1.y + acc1.z + acc1.w;
#pragma unroll
    for (int o = 16; o > 0; o >>= 1) part += __shfl_xor_sync(0xFFFFFFFFu, part, o);

    float4* hp4 = (float4*)(g_hproj + (size_t)node * DOUT);
    hp4[lane] = acc0;
    if (v2) hp4[lane + 32] = acc1;
    if (lane == 0) g_e[node] = part * (1.f / 232.f);
}

// ---------------- per-graph softmax: alpha only ----------------
__global__ __launch_bounds__(128) void graph_alpha(float* __restrict__ out_alpha) {
    const int g = blockIdx.x;
    const int tid = threadIdx.x;
    __shared__ float sh[128];
    const int base = g * NPG;

    float v = (tid < NPG) ? g_e[base + tid] : -1e30f;
    sh[tid] = v; __syncthreads();
    for (int o = 64; o > 0; o >>= 1) {
        if (tid < o) sh[tid] = fmaxf(sh[tid], sh[tid + o]);
        __syncthreads();
    }
    float m = sh[0]; __syncthreads();
    float ex = (tid < NPG) ? expf(v - m) : 0.f;
    sh[tid] = ex; __syncthreads();
    for (int o = 64; o > 0; o >>= 1) {
        if (tid < o) sh[tid] += sh[tid + o];
        __syncthreads();
    }
    if (tid < NPG) out_alpha[base + tid] = ex / sh[0];
}

// ---------------- scale: out_hw = alpha * hproj, grid (NGRAPH*4) ----------------
__global__ __launch_bounds__(128) void scale_hw(const float* __restrict__ out_alpha,
                                                float* __restrict__ out_hw) {
    const int g = blockIdx.x >> 2;
    const int chunk = blockIdx.x & 3;
    const int wid = threadIdx.x >> 5;
    const int lane = threadIdx.x & 31;
    const int base = g * NPG;
    const int rlo = chunk * 29;

    for (int r = rlo + wid; r < rlo + 29; r += 4) {
        float a = out_alpha[base + r];
        const float4* s4 = (const float4*)(g_hproj + (size_t)(base + r) * DOUT);
        float4* d4 = (float4*)(out_hw + (size_t)(base + r) * DOUT);
        float4 x = s4[lane];
        d4[lane] = make_float4(a * x.x, a * x.y, a * x.z, a * x.w);
        if (lane < 26) {
            float4 y = s4[lane + 32];
            d4[lane + 32] = make_float4(a * y.x, a * y.y, a * y.z, a * y.w);
        }
    }
}

// ---------------- launch ----------------
extern "C" void kernel_launch(void* const* d_in, const int* in_sizes, int n_in,
                              void* d_out, int out_size) {
    const float* h    = (const float*)d_in[0];
    const int*   edge = (const int*)  d_in[1];   // row 0 = src
    const float* Wq = (const float*)d_in[3];
    const float* Wk = (const float*)d_in[4];
    const float* Wv = (const float*)d_in[5];
    const float* Ws = (const float*)d_in[6];
    float* out = (float*)d_out;   // [0:59392) alpha_map, then h_weighted [N,232]

    cudaFuncSetAttribute(gemm_hmma, cudaFuncAttributeMaxDynamicSharedMemorySize,
                         SM_BYTES);

    detect_dtype<<<1, 32>>>(edge);
    conv_h<<<(N_NODES * HID / 4 + 255) / 256, 256>>>(h);
    pack_w<<<(HID * DOUT + 255) / 256, 256>>>(Wq, Wk, Wv, Ws);
    dim3 ggrid(NPAD / TN, N_NODES / TM);   // (8, 464)
    gemm_hmma<<<ggrid, 256, SM_BYTES>>>();
    attn_kernel<<<N_NODES / 8, 256>>>(edge);
    graph_alpha<<<NGRAPH, 128>>>(out);
    scale_hw<<<NGRAPH * 4, 128>>>(out, out + N_NODES);
}

// round 14
// speedup vs baseline: 1.1735x; 1.1093x over previous
#include <cuda_runtime.h>
#include <cuda_fp16.h>
#include <math.h>
#include <stdint.h>

#define N_NODES 59392
#define HID     256
#define DOUT    232
#define DH      116
#define NPG     116
#define NGRAPH  512
#define NPAD    1024          // padded GEMM N
#define KVS     464           // kv16 row stride (halves): k[232] | v[232]

// GEMM tiling
#define TM 128
#define TN 128
#define KC 32
#define NCH (HID / KC)        // 8
#define NSTG 4
#define ASTR 40               // 32 + 8 halves
#define BSTR 136              // 128 + 8 halves
#define A_T (TM * ASTR)
#define B_T (KC * BSTR)
#define STG_H (A_T + B_T)
#define SM_BYTES (NSTG * STG_H * 2)   // 75776 B

// ---------------- device scratch (no allocations allowed) ----------------
__device__ __align__(16) __half g_hf16[(size_t)N_NODES * HID];   // h in fp16
__device__ __align__(16) __half g_Wh[HID * NPAD];                // packed weights fp16
__device__ __align__(16) float  g_q [(size_t)N_NODES * DOUT];    // q fp32
__device__ __align__(16) float  g_s [(size_t)N_NODES * DOUT];    // skip (h@Ws) fp32
__device__ __align__(16) __half g_kv16[(size_t)N_NODES * KVS];   // k|v fp16
__device__ __align__(16) float  g_hproj[(size_t)N_NODES * DOUT]; // [N,232]
__device__ float g_e[N_NODES];
__device__ int   g_is64;

// ---------------- helpers ----------------
__device__ __forceinline__ uint32_t s2u(const void* p) {
    uint32_t a;
    asm("{ .reg .u64 t; cvta.to.shared.u64 t, %1; cvt.u32.u64 %0, t; }"
        : "=r"(a) : "l"(p));
    return a;
}
__device__ __forceinline__ void cp16(uint32_t saddr, const void* gaddr) {
    asm volatile("cp.async.cg.shared.global [%0], [%1], 16;"
                 :: "r"(saddr), "l"(gaddr));
}
__device__ __forceinline__ void ldm4(uint32_t& r0, uint32_t& r1, uint32_t& r2,
                                     uint32_t& r3, uint32_t a) {
    asm volatile("ldmatrix.sync.aligned.m8n8.x4.shared.b16 {%0,%1,%2,%3}, [%4];"
                 : "=r"(r0), "=r"(r1), "=r"(r2), "=r"(r3) : "r"(a));
}
__device__ __forceinline__ void ldm4t(uint32_t& r0, uint32_t& r1, uint32_t& r2,
                                      uint32_t& r3, uint32_t a) {
    asm volatile("ldmatrix.sync.aligned.m8n8.x4.trans.shared.b16 {%0,%1,%2,%3}, [%4];"
                 : "=r"(r0), "=r"(r1), "=r"(r2), "=r"(r3) : "r"(a));
}
__device__ __forceinline__ void mma_f16(float& d0, float& d1, float& d2, float& d3,
                                        uint32_t a0, uint32_t a1, uint32_t a2, uint32_t a3,
                                        uint32_t b0, uint32_t b1) {
    asm volatile("mma.sync.aligned.m16n8k16.row.col.f32.f16.f16.f32 "
                 "{%0,%1,%2,%3}, {%4,%5,%6,%7}, {%8,%9}, {%0,%1,%2,%3};"
                 : "+f"(d0), "+f"(d1), "+f"(d2), "+f"(d3)
                 : "r"(a0), "r"(a1), "r"(a2), "r"(a3), "r"(b0), "r"(b1));
}
__device__ __forceinline__ float dot4h(float4 q, uint2 kv) {
    float2 f01 = __half22float2(*(const __half2*)&kv.x);
    float2 f23 = __half22float2(*(const __half2*)&kv.y);
    return q.x * f01.x + q.y * f01.y + q.z * f23.x + q.w * f23.y;
}

// ---------------- edge_index dtype probe ----------------
__global__ void detect_dtype(const int* __restrict__ e32) {
    if (threadIdx.x == 0 && blockIdx.x == 0) {
        int z = (e32[1] == 0) & (e32[3] == 0) & (e32[5] == 0) &
                (e32[7] == 0) & (e32[9] == 0);
        g_is64 = z;
    }
}

// ---------------- convert h -> fp16 ----------------
__global__ __launch_bounds__(256) void conv_h(const float* __restrict__ h) {
    size_t i = ((size_t)blockIdx.x * blockDim.x + threadIdx.x) * 4;
    if (i < (size_t)N_NODES * HID) {
        float4 v = *(const float4*)(h + i);
        __half2* dst = (__half2*)(g_hf16 + i);
        dst[0] = __floats2half2_rn(v.x, v.y);
        dst[1] = __floats2half2_rn(v.z, v.w);
    }
}

// ---------------- pack Wq|Wk|Wv|Ws into g_Wh[256,1024] fp16 ----------------
__global__ void pack_w(const float* __restrict__ Wq, const float* __restrict__ Wk,
                       const float* __restrict__ Wv, const float* __restrict__ Ws) {
    int idx = blockIdx.x * blockDim.x + threadIdx.x;
    if (idx >= HID * DOUT) return;
    int k = idx / DOUT, n = idx % DOUT;
    __half* row = g_Wh + (size_t)k * NPAD;
    row[n]       = __float2half_rn(Wq[idx]);
    row[232 + n] = __float2half_rn(Wk[idx]);
    row[464 + n] = __float2half_rn(Wv[idx]);
    row[696 + n] = __float2half_rn(Ws[idx]);
}

// ---------------- fp16 HGEMM: 4-stage cp.async pipeline ----------------
__device__ __forceinline__ void load_chunk(uint32_t stg, int row0, int col0,
                                           int k0, int tid) {
    uint32_t as = stg, bs = stg + A_T * 2;
#pragma unroll
    for (int j = 0; j < 2; j++) {
        int idx = tid + 256 * j;
        int m  = idx >> 2;
        int kq = (idx & 3) * 8;
        cp16(as + (m * ASTR + kq) * 2,
             g_hf16 + (size_t)(row0 + m) * HID + k0 + kq);
    }
#pragma unroll
    for (int j = 0; j < 2; j++) {
        int idx = tid + 256 * j;
        int kr = idx >> 4;
        int n  = (idx & 15) * 8;
        cp16(bs + (kr * BSTR + n) * 2,
             g_Wh + (size_t)(k0 + kr) * NPAD + col0 + n);
    }
    asm volatile("cp.async.commit_group;" ::: "memory");
}

__device__ __forceinline__ void compute_chunk(uint32_t stg, int wm, int wn,
                                              int lane, float d[4][4][4]) {
    uint32_t as = stg, bs = stg + A_T * 2;
    const int lrow = lane & 15;
    const int lsel = (lane >> 4) << 3;
#pragma unroll
    for (int kk = 0; kk < KC; kk += 16) {
        uint32_t af[4][4], bf[4][2];
#pragma unroll
        for (int mi = 0; mi < 4; mi++) {
            uint32_t a = as + ((wm + mi * 16 + lrow) * ASTR + kk + lsel) * 2;
            ldm4(af[mi][0], af[mi][1], af[mi][2], af[mi][3], a);
        }
#pragma unroll
        for (int nj = 0; nj < 2; nj++) {
            uint32_t a = bs + ((kk + lrow) * BSTR + wn + nj * 16 + lsel) * 2;
            uint32_t r0, r1, r2, r3;
            ldm4t(r0, r1, r2, r3, a);
            bf[nj * 2][0] = r0;     bf[nj * 2][1] = r1;
            bf[nj * 2 + 1][0] = r2; bf[nj * 2 + 1][1] = r3;
        }
#pragma unroll
        for (int mi = 0; mi < 4; mi++)
#pragma unroll
            for (int ni = 0; ni < 4; ni++)
                mma_f16(d[mi][ni][0], d[mi][ni][1], d[mi][ni][2], d[mi][ni][3],
                        af[mi][0], af[mi][1], af[mi][2], af[mi][3],
                        bf[ni][0], bf[ni][1]);
    }
}

// store one float2 result to the right destination buffer by column range
__device__ __forceinline__ void store_pair(int row, int col, float x, float y) {
    if (col < 232) {
        *(float2*)&g_q[(size_t)row * DOUT + col] = make_float2(x, y);
    } else if (col < 696) {
        *(__half2*)&g_kv16[(size_t)row * KVS + (col - 232)] =
            __floats2half2_rn(x, y);
    } else if (col < 928) {
        *(float2*)&g_s[(size_t)row * DOUT + (col - 696)] = make_float2(x, y);
    }
}

__global__ __launch_bounds__(256) void gemm_hmma() {
    extern __shared__ __half smem[];
    const uint32_t sbase = s2u(smem);

    const int tid  = threadIdx.x;
    const int wid  = tid >> 5;
    const int lane = tid & 31;
    const int wm = (wid & 1) * 64;
    const int wn = (wid >> 1) * 32;
    const int r  = lane >> 2;
    const int c  = lane & 3;
    const int row0 = blockIdx.y * TM;
    const int col0 = blockIdx.x * TN;

    float d[4][4][4];
#pragma unroll
    for (int mi = 0; mi < 4; mi++)
#pragma unroll
        for (int ni = 0; ni < 4; ni++)
#pragma unroll
            for (int t = 0; t < 4; t++) d[mi][ni][t] = 0.f;

    load_chunk(sbase + 0 * STG_H * 2, row0, col0, 0 * KC, tid);
    load_chunk(sbase + 1 * STG_H * 2, row0, col0, 1 * KC, tid);
    load_chunk(sbase + 2 * STG_H * 2, row0, col0, 2 * KC, tid);

#pragma unroll
    for (int ch = 0; ch < NCH; ch++) {
        if (ch <= NCH - 3)
            asm volatile("cp.async.wait_group 2;" ::: "memory");
        else if (ch == NCH - 2)
            asm volatile("cp.async.wait_group 1;" ::: "memory");
        else
            asm volatile("cp.async.wait_group 0;" ::: "memory");
        __syncthreads();
        if (ch + 3 < NCH)
            load_chunk(sbase + ((ch + 3) & 3) * STG_H * 2, row0, col0,
                       (ch + 3) * KC, tid);
        compute_chunk(sbase + (ch & 3) * STG_H * 2, wm, wn, lane, d);
    }

    // epilogue: route each float2 to q (fp32) | kv (fp16) | s (fp32)
    const int c2 = c * 2;
#pragma unroll
    for (int mi = 0; mi < 4; mi++) {
#pragma unroll
        for (int ni = 0; ni < 4; ni++) {
            int row = row0 + wm + mi * 16 + r;
            int col = col0 + wn + ni * 8 + c2;
            store_pair(row,     col, d[mi][ni][0], d[mi][ni][1]);
            store_pair(row + 8, col, d[mi][ni][2], d[mi][ni][3]);
        }
    }
}

// ---------------- per-node edge attention (fp16 k/v gathers) ----------------
__global__ __launch_bounds__(256) void attn_kernel(const int* __restrict__ e32) {
    const int warp = threadIdx.x >> 5;
    const int lane = threadIdx.x & 31;
    const int node = blockIdx.x * 8 + warp;
    if (node >= N_NODES) return;
    const int is64 = g_is64;
    const bool v2 = lane < 26;          // second 4-group valid (58 groups)
    const bool h0 = lane < 29;          // first group belongs to head 0
    const float4 z4 = make_float4(0.f, 0.f, 0.f, 0.f);
    const uint2  z2 = make_uint2(0u, 0u);

    const float4* q4 = (const float4*)(g_q + (size_t)node * DOUT);
    float4 q0 = q4[lane];
    float4 q1 = v2 ? q4[lane + 32] : z4;

    int src[8];
#pragma unroll
    for (int e = 0; e < 8; e++) {
        int ei = node * 8 + e;
        src[e] = is64 ? e32[2 * ei] : e32[ei];
    }

    float s0[8], s1[8];
#pragma unroll
    for (int g = 0; g < 2; g++) {
        uint2 k0[4], k1[4];
#pragma unroll
        for (int e = 0; e < 4; e++) {
            const uint2* kp = (const uint2*)(g_kv16 + (size_t)src[g * 4 + e] * KVS);
            k0[e] = kp[lane];
            k1[e] = v2 ? kp[lane + 32] : z2;
        }
#pragma unroll
        for (int e = 0; e < 4; e++) {
            float p0 = dot4h(q0, k0[e]);
            float p1 = dot4h(q1, k1[e]);
            float a0 = h0 ? p0 : 0.f;
            float a1 = h0 ? p1 : p0 + p1;
#pragma unroll
            for (int o = 16; o > 0; o >>= 1) {
                a0 += __shfl_xor_sync(0xFFFFFFFFu, a0, o);
                a1 += __shfl_xor_sync(0xFFFFFFFFu, a1, o);
            }
            s0[g * 4 + e] = a0; s1[g * 4 + e] = a1;
        }
    }

    const float scale = rsqrtf((float)DH);
    float m0 = -1e30f, m1 = -1e30f;
#pragma unroll
    for (int e = 0; e < 8; e++) {
        s0[e] *= scale; s1[e] *= scale;
        m0 = fmaxf(m0, s0[e]); m1 = fmaxf(m1, s1[e]);
    }
    float sum0 = 0.f, sum1 = 0.f;
    float w0[8], w1[8];
#pragma unroll
    for (int e = 0; e < 8; e++) {
        w0[e] = expf(s0[e] - m0); sum0 += w0[e];
        w1[e] = expf(s1[e] - m1); sum1 += w1[e];
    }
    float inv0 = 1.f / (sum0 + 1e-16f);
    float inv1 = 1.f / (sum1 + 1e-16f);
#pragma unroll
    for (int e = 0; e < 8; e++) { w0[e] *= inv0; w1[e] *= inv1; }

    // skip init (fp32 from g_s), accumulate alpha*v with fp16 v gathers
    const float4* s4p = (const float4*)(g_s + (size_t)node * DOUT);
    float4 acc0 = s4p[lane];
    float4 acc1 = v2 ? s4p[lane + 32] : z4;
#pragma unroll
    for (int g = 0; g < 2; g++) {
        uint2 vv0[4], vv1[4];
#pragma unroll
        for (int e = 0; e < 4; e++) {
            const uint2* vp = (const uint2*)(g_kv16 + (size_t)src[g * 4 + e] * KVS + 232);
            vv0[e] = vp[lane];
            vv1[e] = v2 ? vp[lane + 32] : z2;
        }
#pragma unroll
        for (int e = 0; e < 4; e++) {
            float wf = h0 ? w0[g * 4 + e] : w1[g * 4 + e];
            float ws = w1[g * 4 + e];
            float2 a01 = __half22float2(*(const __half2*)&vv0[e].x);
            float2 a23 = __half22float2(*(const __half2*)&vv0[e].y);
            acc0.x += wf * a01.x; acc0.y += wf * a01.y;
            acc0.z += wf * a23.x; acc0.w += wf * a23.y;
            float2 b01 = __half22float2(*(const __half2*)&vv1[e].x);
            float2 b23 = __half22float2(*(const __half2*)&vv1[e].y);
            acc1.x += ws * b01.x; acc1.y += ws * b01.y;
            acc1.z += ws * b23.x; acc1.w += ws * b23.y;
        }
    }

    float part = acc0.x + acc0.y + acc0.z + acc0.w
               + acc1.x + acc1.y + acc1.z + acc1.w;
#pragma unroll
    for (int o = 16; o > 0; o >>= 1) part += __shfl_xor_sync(0xFFFFFFFFu, part, o);

    float4* hp4 = (float4*)(g_hproj + (size_t)node * DOUT);
    hp4[lane] = acc0;
    if (v2) hp4[lane + 32] = acc1;
    if (lane == 0) g_e[node] = part * (1.f / 232.f);
}

// ---------------- per-graph softmax: alpha only ----------------
__global__ __launch_bounds__(128) void graph_alpha(float* __restrict__ out_alpha) {
    const int g = blockIdx.x;
    const int tid = threadIdx.x;
    __shared__ float sh[128];
    const int base = g * NPG;

    float v = (tid < NPG) ? g_e[base + tid] : -1e30f;
    sh[tid] = v; __syncthreads();
    for (int o = 64; o > 0; o >>= 1) {
        if (tid < o) sh[tid] = fmaxf(sh[tid], sh[tid + o]);
        __syncthreads();
    }
    float m = sh[0]; __syncthreads();
    float ex = (tid < NPG) ? expf(v - m) : 0.f;
    sh[tid] = ex; __syncthreads();
    for (int o = 64; o > 0; o >>= 1) {
        if (tid < o) sh[tid] += sh[tid + o];
        __syncthreads();
    }
    if (tid < NPG) out_alpha[base + tid] = ex / sh[0];
}

// ---------------- scale: out_hw = alpha * hproj, grid (NGRAPH*4) ----------------
__global__ __launch_bounds__(128) void scale_hw(const float* __restrict__ out_alpha,
                                                float* __restrict__ out_hw) {
    const int g = blockIdx.x >> 2;
    const int chunk = blockIdx.x & 3;
    const int wid = threadIdx.x >> 5;
    const int lane = threadIdx.x & 31;
    const int base = g * NPG;
    const int rlo = chunk * 29;

    for (int r = rlo + wid; r < rlo + 29; r += 4) {
        float a = out_alpha[base + r];
        const float4* s4 = (const float4*)(g_hproj + (size_t)(base + r) * DOUT);
        float4* d4 = (float4*)(out_hw + (size_t)(base + r) * DOUT);
        float4 x = s4[lane];
        d4[lane] = make_float4(a * x.x, a * x.y, a * x.z, a * x.w);
        if (lane < 26) {
            float4 y = s4[lane + 32];
            d4[lane + 32] = make_float4(a * y.x, a * y.y, a * y.z, a * y.w);
        }
    }
}

// ---------------- launch ----------------
extern "C" void kernel_launch(void* const* d_in, const int* in_sizes, int n_in,
                              void* d_out, int out_size) {
    const float* h    = (const float*)d_in[0];
    const int*   edge = (const int*)  d_in[1];   // row 0 = src
    const float* Wq = (const float*)d_in[3];
    const float* Wk = (const float*)d_in[4];
    const float* Wv = (const float*)d_in[5];
    const float* Ws = (const float*)d_in[6];
    float* out = (float*)d_out;   // [0:59392) alpha_map, then h_weighted [N,232]

    cudaFuncSetAttribute(gemm_hmma, cudaFuncAttributeMaxDynamicSharedMemorySize,
                         SM_BYTES);

    detect_dtype<<<1, 32>>>(edge);
    conv_h<<<(N_NODES * HID / 4 + 255) / 256, 256>>>(h);
    pack_w<<<(HID * DOUT + 255) / 256, 256>>>(Wq, Wk, Wv, Ws);
    dim3 ggrid(NPAD / TN, N_NODES / TM);   // (8, 464)
    gemm_hmma<<<ggrid, 256, SM_BYTES>>>();
    attn_kernel<<<N_NODES / 8, 256>>>(edge);
    graph_alpha<<<NGRAPH, 128>>>(out);
    scale_hw<<<NGRAPH * 4, 128>>>(out, out + N_NODES);
}